// round 1
// baseline (speedup 1.0000x reference)
#include <cuda_runtime.h>

// ---------------------------------------------------------------------------
// Decoder step: attention (B=128, L=2048, H=256) + 2x LSTM cell.
//
// Kernel 1 (attn): per-batch flash-style online softmax, single pass over
//   encoder_outputs (256 MB -> HBM bound). Also writes the transposed GEMM
//   inputs X1T = [ctx ; hidden1] (512 x 128) and the static rows of
//   X2T = [embed ; (h1 later) ; hidden2] (768 x 128).
// Kernel 2/3 (lstm<LAYER>): gates GEMM M=128,N=1024,K=512/768 with fused
//   bias + sigmoid/tanh epilogue. Tile: 2 h-indices x 4 gate types x 128
//   batches per block, grid=128 -> weights read once chip-wide.
// ---------------------------------------------------------------------------

#define B_ 128
#define H_ 256
#define L_ 2048

__device__ float g_X1T[512 * 128];   // rows 0..255 ctx, 256..511 hidden1
__device__ float g_X2T[768 * 128];   // rows 0..255 embed, 256..511 h1, 512..767 hidden2

// ---------------- attention ------------------------------------------------

__device__ __forceinline__ void online_step(
    const float4& ea, const float4& eb, const float4& ha, const float4& hb,
    float& m, float& d, float* c)
{
    float s = ea.x * ha.x + ea.y * ha.y + ea.z * ha.z + ea.w * ha.w
            + eb.x * hb.x + eb.y * hb.y + eb.z * hb.z + eb.w * hb.w;
#pragma unroll
    for (int off = 16; off; off >>= 1)
        s += __shfl_xor_sync(0xffffffffu, s, off);
    float mn = fmaxf(m, s);
    float es = __expf(s - mn);
    float em = __expf(m - mn);
    d = d * em + es;
    c[0] = fmaf(c[0], em, es * ea.x);
    c[1] = fmaf(c[1], em, es * ea.y);
    c[2] = fmaf(c[2], em, es * ea.z);
    c[3] = fmaf(c[3], em, es * ea.w);
    c[4] = fmaf(c[4], em, es * eb.x);
    c[5] = fmaf(c[5], em, es * eb.y);
    c[6] = fmaf(c[6], em, es * eb.z);
    c[7] = fmaf(c[7], em, es * eb.w);
    m = mn;
}

__global__ __launch_bounds__(256) void attn_kernel(
    const float* __restrict__ enc,       // (B, L, H)
    const float* __restrict__ hidden1,   // (B, H)
    const float* __restrict__ embed,     // (B, E)
    const float* __restrict__ hidden2)   // (B, H)
{
    const int b    = blockIdx.x;
    const int tid  = threadIdx.x;
    const int w    = tid >> 5;
    const int lane = tid & 31;

    __shared__ float h1s[H_];
    __shared__ float ctx_s[8][H_];
    __shared__ float m_s[8], d_s[8];

    h1s[tid] = hidden1[b * H_ + tid];
    __syncthreads();

    const float4 ha = *reinterpret_cast<const float4*>(&h1s[lane * 4]);
    const float4 hb = *reinterpret_cast<const float4*>(&h1s[128 + lane * 4]);

    const float* encb = enc + (size_t)b * (L_ * H_);

    // 4 independent online streams per warp: stream j handles l = w + 8j + 32i
    float m[4], d[4], c[4][8];
    float4 ea[4], eb[4];
    const float* p[4];
#pragma unroll
    for (int j = 0; j < 4; j++) {
        m[j] = -1e30f; d[j] = 0.f;
#pragma unroll
        for (int q = 0; q < 8; q++) c[j][q] = 0.f;
        p[j]  = encb + (size_t)(w + 8 * j) * H_ + lane * 4;
        ea[j] = *reinterpret_cast<const float4*>(p[j]);
        eb[j] = *reinterpret_cast<const float4*>(p[j] + 128);
    }

    const int STRIDE = 32 * H_;  // 32 rows per iteration across the 4 streams
    for (int i = 0; i < 63; i++) {
        float4 na[4], nb[4];
#pragma unroll
        for (int j = 0; j < 4; j++) {
            na[j] = *reinterpret_cast<const float4*>(p[j] + STRIDE);
            nb[j] = *reinterpret_cast<const float4*>(p[j] + STRIDE + 128);
        }
#pragma unroll
        for (int j = 0; j < 4; j++)
            online_step(ea[j], eb[j], ha, hb, m[j], d[j], c[j]);
#pragma unroll
        for (int j = 0; j < 4; j++) {
            ea[j] = na[j]; eb[j] = nb[j]; p[j] += STRIDE;
        }
    }
#pragma unroll
    for (int j = 0; j < 4; j++)
        online_step(ea[j], eb[j], ha, hb, m[j], d[j], c[j]);

    // merge the 4 streams into stream 0
#pragma unroll
    for (int j = 1; j < 4; j++) {
        float M2 = fmaxf(m[0], m[j]);
        float e0 = __expf(m[0] - M2);
        float e1 = __expf(m[j] - M2);
        d[0] = d[0] * e0 + d[j] * e1;
#pragma unroll
        for (int q = 0; q < 8; q++)
            c[0][q] = c[0][q] * e0 + c[j][q] * e1;
        m[0] = M2;
    }

    // per-warp partials to smem
#pragma unroll
    for (int q = 0; q < 4; q++) {
        ctx_s[w][lane * 4 + q]       = c[0][q];
        ctx_s[w][128 + lane * 4 + q] = c[0][4 + q];
    }
    if (lane == 0) { m_s[w] = m[0]; d_s[w] = d[0]; }
    __syncthreads();

    // block combine: thread t owns h-index t
    float M = m_s[0];
#pragma unroll
    for (int ww = 1; ww < 8; ww++) M = fmaxf(M, m_s[ww]);
    float D = 0.f, C = 0.f;
#pragma unroll
    for (int ww = 0; ww < 8; ww++) {
        float e = __expf(m_s[ww] - M);
        D += d_s[ww] * e;
        C += ctx_s[ww][tid] * e;
    }
    float ctxv = C / D;

    // transposed GEMM inputs (column b)
    g_X1T[tid * B_ + b]          = ctxv;              // ctx
    g_X1T[(H_ + tid) * B_ + b]   = h1s[tid];          // hidden1
    g_X2T[tid * B_ + b]          = embed[b * H_ + tid];
    g_X2T[(512 + tid) * B_ + b]  = hidden2[b * H_ + tid];
}

// ---------------- LSTM cell (gates GEMM + epilogue) -------------------------

__device__ __forceinline__ float sigmoidf_(float x) {
    return 1.f / (1.f + __expf(-x));
}

template <int LAYER>
__global__ __launch_bounds__(256) void lstm_kernel(
    const float* __restrict__ w_ih, const float* __restrict__ w_hh,
    const float* __restrict__ b_ih, const float* __restrict__ b_hh,
    const float* __restrict__ c_prev,
    float* __restrict__ h_out, float* __restrict__ c_out,
    float* __restrict__ h_dup)
{
    constexpr int K  = (LAYER == 1) ? 512 : 768;
    constexpr int KA = (LAYER == 1) ? 256 : 512;
    constexpr int KB = 256;
    constexpr int NC = K / 16;  // 16-k chunks, double buffered

    const float* XT = (LAYER == 1) ? g_X1T : g_X2T;

    __shared__ float Ws[8 * K];           // 8 gate rows (2 h x 4 types)
    __shared__ float Xs[2][16 * B_];      // 16 k-rows x 128 batches, x2

    const int tid = threadIdx.x;
    const int h0  = blockIdx.x * 2;

    // load weight rows: r = hloc*4 + type
    for (int idx = tid; idx < 8 * K; idx += 256) {
        int r = idx / K;
        int k = idx - r * K;
        int g = (r & 3) * H_ + h0 + (r >> 2);
        Ws[idx] = (k < KA) ? w_ih[(size_t)g * KA + k]
                           : w_hh[(size_t)g * KB + (k - KA)];
    }

    // preload X chunk 0 (contiguous 16*128 floats)
    {
        const float4* src = reinterpret_cast<const float4*>(XT);
        float4* dst = reinterpret_cast<float4*>(&Xs[0][0]);
        dst[tid]       = src[tid];
        dst[256 + tid] = src[256 + tid];
    }
    __syncthreads();

    const int b    = tid & 127;
    const int hloc = tid >> 7;
    const int h    = h0 + hloc;

    float acc[4];
#pragma unroll
    for (int j = 0; j < 4; j++)
        acc[j] = b_ih[j * H_ + h] + b_hh[j * H_ + h];

    const float* Wp = &Ws[(hloc * 4) * K];

    for (int cchunk = 0; cchunk < NC; cchunk++) {
        const int buf = cchunk & 1;
        if (cchunk + 1 < NC) {
            const float4* src = reinterpret_cast<const float4*>(XT + (cchunk + 1) * 16 * B_);
            float4* dst = reinterpret_cast<float4*>(&Xs[buf ^ 1][0]);
            dst[tid]       = src[tid];
            dst[256 + tid] = src[256 + tid];
        }
#pragma unroll
        for (int kk = 0; kk < 16; kk += 4) {
            const int kg = cchunk * 16 + kk;
            float x0 = Xs[buf][(kk + 0) * B_ + b];
            float x1 = Xs[buf][(kk + 1) * B_ + b];
            float x2 = Xs[buf][(kk + 2) * B_ + b];
            float x3 = Xs[buf][(kk + 3) * B_ + b];
#pragma unroll
            for (int j = 0; j < 4; j++) {
                float4 wv = *reinterpret_cast<const float4*>(&Wp[j * K + kg]);
                acc[j] = fmaf(x0, wv.x, acc[j]);
                acc[j] = fmaf(x1, wv.y, acc[j]);
                acc[j] = fmaf(x2, wv.z, acc[j]);
                acc[j] = fmaf(x3, wv.w, acc[j]);
            }
        }
        __syncthreads();
    }

    // epilogue: i,f,g,o -> c_new, h_new
    float ig = sigmoidf_(acc[0]);
    float fg = sigmoidf_(acc[1]);
    float gg = tanhf(acc[2]);
    float og = sigmoidf_(acc[3]);
    float cn = fmaf(fg, c_prev[b * H_ + h], ig * gg);
    float hn = og * tanhf(cn);

    c_out[b * H_ + h] = cn;
    h_out[b * H_ + h] = hn;
    if (LAYER == 1) {
        // feed LSTM2: X2T rows 256..511 hold h1 transposed
        g_X2T[(H_ + h) * B_ + b] = hn;
    }
    if (h_dup) h_dup[b * H_ + h] = hn;
}

// ---------------- launch -----------------------------------------------------

extern "C" void kernel_launch(void* const* d_in, const int* in_sizes, int n_in,
                              void* d_out, int out_size)
{
    const float* embed   = (const float*)d_in[0];
    const float* enc     = (const float*)d_in[1];
    const float* hidden1 = (const float*)d_in[2];
    const float* cell1   = (const float*)d_in[3];
    const float* hidden2 = (const float*)d_in[4];
    const float* cell2   = (const float*)d_in[5];
    const float* w_ih1   = (const float*)d_in[6];
    const float* w_hh1   = (const float*)d_in[7];
    const float* b_ih1   = (const float*)d_in[8];
    const float* b_hh1   = (const float*)d_in[9];
    const float* w_ih2   = (const float*)d_in[10];
    const float* w_hh2   = (const float*)d_in[11];
    const float* b_ih2   = (const float*)d_in[12];
    const float* b_hh2   = (const float*)d_in[13];
    float* out = (float*)d_out;

    // output layout: [outputs(B*H)] [h1] [c1] [h2] [c2]
    float* o_outputs = out;
    float* o_h1 = out + 32768;
    float* o_c1 = out + 65536;
    float* o_h2 = out + 98304;
    float* o_c2 = out + 131072;

    attn_kernel<<<128, 256>>>(enc, hidden1, embed, hidden2);
    lstm_kernel<1><<<128, 256>>>(w_ih1, w_hh1, b_ih1, b_hh1, cell1,
                                 o_h1, o_c1, nullptr);
    lstm_kernel<2><<<128, 256>>>(w_ih2, w_hh2, b_ih2, b_hh2, cell2,
                                 o_h2, o_c2, o_outputs);
}

// round 2
// speedup vs baseline: 1.0990x; 1.0990x over previous
#include <cuda_runtime.h>

// ---------------------------------------------------------------------------
// Decoder step: attention (B=128, L=2048, H=256) + 2x LSTM cell.
//
// attn_kernel : split-K flash softmax. grid = 128 batches x 4 L-splits,
//               2 blocks/SM. Writes per-split (m, d, unnormalized ctx).
// combine_kernel: merges 4 splits per batch, writes transposed GEMM inputs
//               X1T = [ctx ; hidden1], X2T statics = [embed ; _ ; hidden2].
// lstm_kernel : gates GEMM M=128,N=1024,K=512/768, barrier-free mainloop.
//               Block = 2 h-indices; threads (b=128) x (khalf=2); weights in
//               smem (broadcast), X streamed from L2 coalesced.
// ---------------------------------------------------------------------------

#define B_ 128
#define H_ 256
#define L_ 2048
#define NSPLIT 4
#define LSP (L_ / NSPLIT)   // 512 rows per split

__device__ float g_X1T[512 * 128];
__device__ float g_X2T[768 * 128];
__device__ float g_ctx_part[B_ * NSPLIT * H_];   // [bx][h], bx = b*4+s
__device__ float g_md[B_ * NSPLIT * 2];          // [bx][{m,d}]

// ---------------- attention ------------------------------------------------

__device__ __forceinline__ void online_step(
    const float4& ea, const float4& eb, const float4& ha, const float4& hb,
    float& m, float& d, float* c)
{
    float s = ea.x * ha.x + ea.y * ha.y + ea.z * ha.z + ea.w * ha.w
            + eb.x * hb.x + eb.y * hb.y + eb.z * hb.z + eb.w * hb.w;
#pragma unroll
    for (int off = 16; off; off >>= 1)
        s += __shfl_xor_sync(0xffffffffu, s, off);
    float mn = fmaxf(m, s);
    float es = __expf(s - mn);
    float em = __expf(m - mn);
    d = d * em + es;
    c[0] = fmaf(c[0], em, es * ea.x);
    c[1] = fmaf(c[1], em, es * ea.y);
    c[2] = fmaf(c[2], em, es * ea.z);
    c[3] = fmaf(c[3], em, es * ea.w);
    c[4] = fmaf(c[4], em, es * eb.x);
    c[5] = fmaf(c[5], em, es * eb.y);
    c[6] = fmaf(c[6], em, es * eb.z);
    c[7] = fmaf(c[7], em, es * eb.w);
    m = mn;
}

__global__ __launch_bounds__(256, 2) void attn_kernel(
    const float* __restrict__ enc,       // (B, L, H)
    const float* __restrict__ hidden1)   // (B, H)
{
    const int bx   = blockIdx.x;          // b*NSPLIT + split
    const int b    = bx >> 2;
    const int sp   = bx & 3;
    const int tid  = threadIdx.x;
    const int w    = tid >> 5;
    const int lane = tid & 31;

    __shared__ float h1s[H_];
    __shared__ float ctx_s[8][H_];
    __shared__ float m_s[8], d_s[8];

    h1s[tid] = hidden1[b * H_ + tid];
    __syncthreads();

    const float4 ha = *reinterpret_cast<const float4*>(&h1s[lane * 4]);
    const float4 hb = *reinterpret_cast<const float4*>(&h1s[128 + lane * 4]);

    const float* encb = enc + (size_t)b * (L_ * H_) + (size_t)sp * (LSP * H_);

    // 4 independent online streams per warp: stream j rows = w + 8j + 32i
    float m[4], d[4], c[4][8];
    float4 ea[4], eb[4];
    const float* p[4];
#pragma unroll
    for (int j = 0; j < 4; j++) {
        m[j] = -1e30f; d[j] = 0.f;
#pragma unroll
        for (int q = 0; q < 8; q++) c[j][q] = 0.f;
        p[j]  = encb + (size_t)(w + 8 * j) * H_ + lane * 4;
        ea[j] = *reinterpret_cast<const float4*>(p[j]);
        eb[j] = *reinterpret_cast<const float4*>(p[j] + 128);
    }

    const int STRIDE = 32 * H_;
    const int ITERS  = LSP / 32;          // 16
    for (int i = 0; i < ITERS - 1; i++) {
        float4 na[4], nb[4];
#pragma unroll
        for (int j = 0; j < 4; j++) {
            na[j] = *reinterpret_cast<const float4*>(p[j] + STRIDE);
            nb[j] = *reinterpret_cast<const float4*>(p[j] + STRIDE + 128);
        }
#pragma unroll
        for (int j = 0; j < 4; j++)
            online_step(ea[j], eb[j], ha, hb, m[j], d[j], c[j]);
#pragma unroll
        for (int j = 0; j < 4; j++) {
            ea[j] = na[j]; eb[j] = nb[j]; p[j] += STRIDE;
        }
    }
#pragma unroll
    for (int j = 0; j < 4; j++)
        online_step(ea[j], eb[j], ha, hb, m[j], d[j], c[j]);

    // merge 4 streams
#pragma unroll
    for (int j = 1; j < 4; j++) {
        float M2 = fmaxf(m[0], m[j]);
        float e0 = __expf(m[0] - M2);
        float e1 = __expf(m[j] - M2);
        d[0] = d[0] * e0 + d[j] * e1;
#pragma unroll
        for (int q = 0; q < 8; q++)
            c[0][q] = c[0][q] * e0 + c[j][q] * e1;
        m[0] = M2;
    }

#pragma unroll
    for (int q = 0; q < 4; q++) {
        ctx_s[w][lane * 4 + q]       = c[0][q];
        ctx_s[w][128 + lane * 4 + q] = c[0][4 + q];
    }
    if (lane == 0) { m_s[w] = m[0]; d_s[w] = d[0]; }
    __syncthreads();

    // block combine: thread t owns h-index t; write split partial
    float M = m_s[0];
#pragma unroll
    for (int ww = 1; ww < 8; ww++) M = fmaxf(M, m_s[ww]);
    float D = 0.f, C = 0.f;
#pragma unroll
    for (int ww = 0; ww < 8; ww++) {
        float e = __expf(m_s[ww] - M);
        D += d_s[ww] * e;
        C += ctx_s[ww][tid] * e;
    }
    g_ctx_part[bx * H_ + tid] = C;
    if (tid == 0) { g_md[bx * 2] = M; g_md[bx * 2 + 1] = D; }
}

// ---------------- split combine + transpose pack ----------------------------

__global__ __launch_bounds__(256) void combine_kernel(
    const float* __restrict__ hidden1,
    const float* __restrict__ embed,
    const float* __restrict__ hidden2)
{
    const int b = blockIdx.x;
    const int h = threadIdx.x;

    float ms[NSPLIT], ds[NSPLIT];
#pragma unroll
    for (int s = 0; s < NSPLIT; s++) {
        ms[s] = g_md[(b * NSPLIT + s) * 2];
        ds[s] = g_md[(b * NSPLIT + s) * 2 + 1];
    }
    float M = ms[0];
#pragma unroll
    for (int s = 1; s < NSPLIT; s++) M = fmaxf(M, ms[s]);
    float D = 0.f, C = 0.f;
#pragma unroll
    for (int s = 0; s < NSPLIT; s++) {
        float e = __expf(ms[s] - M);
        D += ds[s] * e;
        C += g_ctx_part[(b * NSPLIT + s) * H_ + h] * e;
    }
    float ctxv = C / D;

    g_X1T[h * B_ + b]          = ctxv;
    g_X1T[(H_ + h) * B_ + b]   = hidden1[b * H_ + h];
    g_X2T[h * B_ + b]          = embed[b * H_ + h];
    g_X2T[(512 + h) * B_ + b]  = hidden2[b * H_ + h];
}

// ---------------- LSTM cell (barrier-free gates GEMM + epilogue) ------------

__device__ __forceinline__ float sigmoidf_(float x) {
    return 1.f / (1.f + __expf(-x));
}

template <int LAYER>
__global__ __launch_bounds__(256) void lstm_kernel(
    const float* __restrict__ w_ih, const float* __restrict__ w_hh,
    const float* __restrict__ b_ih, const float* __restrict__ b_hh,
    const float* __restrict__ c_prev,
    float* __restrict__ h_out, float* __restrict__ c_out,
    float* __restrict__ h_dup)
{
    constexpr int K  = (LAYER == 1) ? 512 : 768;
    constexpr int KA = (LAYER == 1) ? 256 : 512;  // w_ih cols
    constexpr int KH = K / 2;

    const float* __restrict__ XT = (LAYER == 1) ? g_X1T : g_X2T;

    __shared__ float Ws[8 * K];        // row r = hloc*4 + gate
    __shared__ float Rs[128][9];       // khalf-1 partials (padded)

    const int tid   = threadIdx.x;
    const int b     = tid & 127;
    const int khalf = tid >> 7;
    const int h0    = blockIdx.x * 2;

    // preload 8 weight rows (coalesced over k)
    for (int idx = tid; idx < 8 * K; idx += 256) {
        int r = idx / K;
        int k = idx - r * K;
        int g = (r & 3) * H_ + h0 + (r >> 2);
        Ws[idx] = (k < KA) ? w_ih[(size_t)g * KA + k]
                           : w_hh[(size_t)g * 256 + (k - KA)];
    }
    __syncthreads();

    float acc[2][4];
#pragma unroll
    for (int hl = 0; hl < 2; hl++)
#pragma unroll
        for (int g = 0; g < 4; g++)
            acc[hl][g] = (khalf == 0)
                ? (b_ih[g * H_ + h0 + hl] + b_hh[g * H_ + h0 + hl]) : 0.f;

    const int ko = khalf * KH;
    const float* __restrict__ xp = XT + (size_t)ko * B_ + b;

#pragma unroll 4
    for (int kk = 0; kk < KH; kk += 4) {
        float x0 = xp[(kk + 0) * B_];
        float x1 = xp[(kk + 1) * B_];
        float x2 = xp[(kk + 2) * B_];
        float x3 = xp[(kk + 3) * B_];
#pragma unroll
        for (int hl = 0; hl < 2; hl++) {
#pragma unroll
            for (int g = 0; g < 4; g++) {
                float4 wv = *reinterpret_cast<const float4*>(
                    &Ws[(hl * 4 + g) * K + ko + kk]);
                acc[hl][g] = fmaf(x0, wv.x, acc[hl][g]);
                acc[hl][g] = fmaf(x1, wv.y, acc[hl][g]);
                acc[hl][g] = fmaf(x2, wv.z, acc[hl][g]);
                acc[hl][g] = fmaf(x3, wv.w, acc[hl][g]);
            }
        }
    }

    // cross-khalf reduce
    if (khalf == 1) {
#pragma unroll
        for (int hl = 0; hl < 2; hl++)
#pragma unroll
            for (int g = 0; g < 4; g++)
                Rs[b][hl * 4 + g] = acc[hl][g];
    }
    __syncthreads();

    if (khalf == 0) {
#pragma unroll
        for (int hl = 0; hl < 2; hl++) {
            int h = h0 + hl;
            float gi = sigmoidf_(acc[hl][0] + Rs[b][hl * 4 + 0]);
            float gf = sigmoidf_(acc[hl][1] + Rs[b][hl * 4 + 1]);
            float gg = tanhf    (acc[hl][2] + Rs[b][hl * 4 + 2]);
            float go = sigmoidf_(acc[hl][3] + Rs[b][hl * 4 + 3]);
            float cn = fmaf(gf, c_prev[b * H_ + h], gi * gg);
            float hn = go * tanhf(cn);
            c_out[b * H_ + h] = cn;
            h_out[b * H_ + h] = hn;
            if (LAYER == 1) g_X2T[(H_ + h) * B_ + b] = hn;
            if (h_dup)      h_dup[b * H_ + h] = hn;
        }
    }
}

// ---------------- launch -----------------------------------------------------

extern "C" void kernel_launch(void* const* d_in, const int* in_sizes, int n_in,
                              void* d_out, int out_size)
{
    const float* embed   = (const float*)d_in[0];
    const float* enc     = (const float*)d_in[1];
    const float* hidden1 = (const float*)d_in[2];
    const float* cell1   = (const float*)d_in[3];
    const float* hidden2 = (const float*)d_in[4];
    const float* cell2   = (const float*)d_in[5];
    const float* w_ih1   = (const float*)d_in[6];
    const float* w_hh1   = (const float*)d_in[7];
    const float* b_ih1   = (const float*)d_in[8];
    const float* b_hh1   = (const float*)d_in[9];
    const float* w_ih2   = (const float*)d_in[10];
    const float* w_hh2   = (const float*)d_in[11];
    const float* b_ih2   = (const float*)d_in[12];
    const float* b_hh2   = (const float*)d_in[13];
    float* out = (float*)d_out;

    float* o_outputs = out;
    float* o_h1 = out + 32768;
    float* o_c1 = out + 65536;
    float* o_h2 = out + 98304;
    float* o_c2 = out + 131072;

    attn_kernel<<<B_ * NSPLIT, 256>>>(enc, hidden1);
    combine_kernel<<<B_, 256>>>(hidden1, embed, hidden2);
    lstm_kernel<1><<<128, 256>>>(w_ih1, w_hh1, b_ih1, b_hh1, cell1,
                                 o_h1, o_c1, nullptr);
    lstm_kernel<2><<<128, 256>>>(w_ih2, w_hh2, b_ih2, b_hh2, cell2,
                                 o_h2, o_c2, o_outputs);
}

// round 3
// speedup vs baseline: 1.7764x; 1.6164x over previous
#include <cuda_runtime.h>

// ---------------------------------------------------------------------------
// Decoder step: attention (B=128, L=2048, H=256) + 2x LSTM cell.
//
// attn_kernel : split-K flash softmax, grid = 128 x 4 splits.
// combine_kernel: merges splits, writes transposed GEMM inputs.
// lstm_kernel : register-blocked gates GEMM. Block = 8 gate-rows x 128 b,
//   thread tile 4b x 8rows, warps split K 8-ways, X via cp.async double
//   buffer, W tile in smem. Fused bias+sigmoid/tanh epilogue.
// ---------------------------------------------------------------------------

#define B_ 128
#define H_ 256
#define L_ 2048
#define NSPLIT 4
#define LSP (L_ / NSPLIT)

__device__ float g_X1T[512 * 128];
__device__ float g_X2T[768 * 128];
__device__ float g_ctx_part[B_ * NSPLIT * H_];
__device__ float g_md[B_ * NSPLIT * 2];

// ---------------- attention ------------------------------------------------

__device__ __forceinline__ void online_step(
    const float4& ea, const float4& eb, const float4& ha, const float4& hb,
    float& m, float& d, float* c)
{
    float s = ea.x * ha.x + ea.y * ha.y + ea.z * ha.z + ea.w * ha.w
            + eb.x * hb.x + eb.y * hb.y + eb.z * hb.z + eb.w * hb.w;
#pragma unroll
    for (int off = 16; off; off >>= 1)
        s += __shfl_xor_sync(0xffffffffu, s, off);
    float mn = fmaxf(m, s);
    float es = __expf(s - mn);
    float em = __expf(m - mn);
    d = d * em + es;
    c[0] = fmaf(c[0], em, es * ea.x);
    c[1] = fmaf(c[1], em, es * ea.y);
    c[2] = fmaf(c[2], em, es * ea.z);
    c[3] = fmaf(c[3], em, es * ea.w);
    c[4] = fmaf(c[4], em, es * eb.x);
    c[5] = fmaf(c[5], em, es * eb.y);
    c[6] = fmaf(c[6], em, es * eb.z);
    c[7] = fmaf(c[7], em, es * eb.w);
    m = mn;
}

__global__ __launch_bounds__(256, 2) void attn_kernel(
    const float* __restrict__ enc,
    const float* __restrict__ hidden1)
{
    const int bx   = blockIdx.x;
    const int b    = bx >> 2;
    const int sp   = bx & 3;
    const int tid  = threadIdx.x;
    const int w    = tid >> 5;
    const int lane = tid & 31;

    __shared__ float h1s[H_];
    __shared__ float ctx_s[8][H_];
    __shared__ float m_s[8], d_s[8];

    h1s[tid] = hidden1[b * H_ + tid];
    __syncthreads();

    const float4 ha = *reinterpret_cast<const float4*>(&h1s[lane * 4]);
    const float4 hb = *reinterpret_cast<const float4*>(&h1s[128 + lane * 4]);

    const float* encb = enc + (size_t)b * (L_ * H_) + (size_t)sp * (LSP * H_);

    float m[4], d[4], c[4][8];
    float4 ea[4], eb[4];
    const float* p[4];
#pragma unroll
    for (int j = 0; j < 4; j++) {
        m[j] = -1e30f; d[j] = 0.f;
#pragma unroll
        for (int q = 0; q < 8; q++) c[j][q] = 0.f;
        p[j]  = encb + (size_t)(w + 8 * j) * H_ + lane * 4;
        ea[j] = *reinterpret_cast<const float4*>(p[j]);
        eb[j] = *reinterpret_cast<const float4*>(p[j] + 128);
    }

    const int STRIDE = 32 * H_;
    const int ITERS  = LSP / 32;
    for (int i = 0; i < ITERS - 1; i++) {
        float4 na[4], nb[4];
#pragma unroll
        for (int j = 0; j < 4; j++) {
            na[j] = *reinterpret_cast<const float4*>(p[j] + STRIDE);
            nb[j] = *reinterpret_cast<const float4*>(p[j] + STRIDE + 128);
        }
#pragma unroll
        for (int j = 0; j < 4; j++)
            online_step(ea[j], eb[j], ha, hb, m[j], d[j], c[j]);
#pragma unroll
        for (int j = 0; j < 4; j++) {
            ea[j] = na[j]; eb[j] = nb[j]; p[j] += STRIDE;
        }
    }
#pragma unroll
    for (int j = 0; j < 4; j++)
        online_step(ea[j], eb[j], ha, hb, m[j], d[j], c[j]);

#pragma unroll
    for (int j = 1; j < 4; j++) {
        float M2 = fmaxf(m[0], m[j]);
        float e0 = __expf(m[0] - M2);
        float e1 = __expf(m[j] - M2);
        d[0] = d[0] * e0 + d[j] * e1;
#pragma unroll
        for (int q = 0; q < 8; q++)
            c[0][q] = c[0][q] * e0 + c[j][q] * e1;
        m[0] = M2;
    }

#pragma unroll
    for (int q = 0; q < 4; q++) {
        ctx_s[w][lane * 4 + q]       = c[0][q];
        ctx_s[w][128 + lane * 4 + q] = c[0][4 + q];
    }
    if (lane == 0) { m_s[w] = m[0]; d_s[w] = d[0]; }
    __syncthreads();

    float M = m_s[0];
#pragma unroll
    for (int ww = 1; ww < 8; ww++) M = fmaxf(M, m_s[ww]);
    float D = 0.f, C = 0.f;
#pragma unroll
    for (int ww = 0; ww < 8; ww++) {
        float e = __expf(m_s[ww] - M);
        D += d_s[ww] * e;
        C += ctx_s[ww][tid] * e;
    }
    g_ctx_part[bx * H_ + tid] = C;
    if (tid == 0) { g_md[bx * 2] = M; g_md[bx * 2 + 1] = D; }
}

// ---------------- split combine + transpose pack ----------------------------

__global__ __launch_bounds__(256) void combine_kernel(
    const float* __restrict__ hidden1,
    const float* __restrict__ embed,
    const float* __restrict__ hidden2)
{
    const int b = blockIdx.x;
    const int h = threadIdx.x;

    float ms[NSPLIT], ds[NSPLIT];
#pragma unroll
    for (int s = 0; s < NSPLIT; s++) {
        ms[s] = g_md[(b * NSPLIT + s) * 2];
        ds[s] = g_md[(b * NSPLIT + s) * 2 + 1];
    }
    float M = ms[0];
#pragma unroll
    for (int s = 1; s < NSPLIT; s++) M = fmaxf(M, ms[s]);
    float D = 0.f, C = 0.f;
#pragma unroll
    for (int s = 0; s < NSPLIT; s++) {
        float e = __expf(ms[s] - M);
        D += ds[s] * e;
        C += g_ctx_part[(b * NSPLIT + s) * H_ + h] * e;
    }
    float ctxv = C / D;

    g_X1T[h * B_ + b]          = ctxv;
    g_X1T[(H_ + h) * B_ + b]   = hidden1[b * H_ + h];
    g_X2T[h * B_ + b]          = embed[b * H_ + h];
    g_X2T[(512 + h) * B_ + b]  = hidden2[b * H_ + h];
}

// ---------------- LSTM: register-blocked gates GEMM -------------------------

__device__ __forceinline__ float sigmoidf_(float x) {
    return 1.f / (1.f + __expf(-x));
}

__device__ __forceinline__ void cp_async16(void* smem_dst, const void* gmem_src) {
    unsigned saddr = (unsigned)__cvta_generic_to_shared(smem_dst);
    asm volatile("cp.async.cg.shared.global [%0], [%1], 16;\n"
                 :: "r"(saddr), "l"(gmem_src));
}
__device__ __forceinline__ void cp_commit() {
    asm volatile("cp.async.commit_group;\n");
}
__device__ __forceinline__ void cp_wait0() {
    asm volatile("cp.async.wait_group 0;\n");
}

// Block: 8 gate-rows (h0, h0+1 for 4 gates) x 128 batches.
// Thread: 4 batches x 8 rows. Warps split K 8-ways (8 k per 64-k chunk).
template <int LAYER>
__global__ __launch_bounds__(256, 1) void lstm_kernel(
    const float* __restrict__ w_ih, const float* __restrict__ w_hh,
    const float* __restrict__ b_ih, const float* __restrict__ b_hh,
    const float* __restrict__ c_prev,
    float* __restrict__ h_out, float* __restrict__ c_out,
    float* __restrict__ h_dup)
{
    constexpr int K  = (LAYER == 1) ? 512 : 768;
    constexpr int KA = (LAYER == 1) ? 256 : 512;
    constexpr int KC = 64;            // k-chunk
    constexpr int NC = K / KC;

    extern __shared__ float smem[];
    float* Ws = smem;                 // [8][K]
    float* Xs = smem + 8 * K;         // [2][KC*128]
    float* Rs = Xs;                   // overlay after mainloop: [8r][8w][128b]

    const float* __restrict__ XT = (LAYER == 1) ? g_X1T : g_X2T;

    const int tid  = threadIdx.x;
    const int warp = tid >> 5;
    const int lane = tid & 31;
    const int b0   = lane * 4;
    const int h0   = blockIdx.x * 2;

    // preload W tile: 8 rows x K, vectorized
    {
        constexpr int K4 = K / 4;
        for (int idx = tid; idx < 8 * K4; idx += 256) {
            int r  = idx / K4;
            int k  = (idx - r * K4) * 4;
            int g  = (r & 3) * H_ + h0 + (r >> 2);
            float4 v = (k < KA)
                ? *reinterpret_cast<const float4*>(&w_ih[(size_t)g * KA + k])
                : *reinterpret_cast<const float4*>(&w_hh[(size_t)g * 256 + (k - KA)]);
            *reinterpret_cast<float4*>(&Ws[r * K + k]) = v;
        }
    }

    // prologue: async-load chunk 0
    {
        const float* src = XT + tid * 4;
        float* dst = Xs + tid * 4;
#pragma unroll
        for (int it = 0; it < (KC * 128) / (256 * 4); it++)
            cp_async16(dst + it * 1024, src + it * 1024);
        cp_commit();
    }

    float acc[4][8];
#pragma unroll
    for (int j = 0; j < 4; j++)
#pragma unroll
        for (int r = 0; r < 8; r++) acc[j][r] = 0.f;

    for (int c = 0; c < NC; c++) {
        const int buf = c & 1;
        cp_wait0();
        __syncthreads();

        if (c + 1 < NC) {
            const float* src = XT + (size_t)(c + 1) * KC * 128 + tid * 4;
            float* dst = Xs + (buf ^ 1) * (KC * 128) + tid * 4;
#pragma unroll
            for (int it = 0; it < (KC * 128) / (256 * 4); it++)
                cp_async16(dst + it * 1024, src + it * 1024);
            cp_commit();
        }

        // compute: this warp's k-slice = [warp*8, warp*8+8), 2 groups of 4
        const float* xb = Xs + buf * (KC * 128) + (warp * 8) * 128;
        const int kg = c * KC + warp * 8;
#pragma unroll
        for (int g2 = 0; g2 < 2; g2++) {
            float4 xv[4];
#pragma unroll
            for (int kk = 0; kk < 4; kk++)
                xv[kk] = *reinterpret_cast<const float4*>(
                    &xb[(g2 * 4 + kk) * 128 + b0]);
            float wv[8][4];
#pragma unroll
            for (int r = 0; r < 8; r++)
                *reinterpret_cast<float4*>(wv[r]) =
                    *reinterpret_cast<const float4*>(&Ws[r * K + kg + g2 * 4]);
#pragma unroll
            for (int kk = 0; kk < 4; kk++) {
#pragma unroll
                for (int r = 0; r < 8; r++) {
                    acc[0][r] = fmaf(xv[kk].x, wv[r][kk], acc[0][r]);
                    acc[1][r] = fmaf(xv[kk].y, wv[r][kk], acc[1][r]);
                    acc[2][r] = fmaf(xv[kk].z, wv[r][kk], acc[2][r]);
                    acc[3][r] = fmaf(xv[kk].w, wv[r][kk], acc[3][r]);
                }
            }
        }
    }

    // cross-warp reduce via smem (overlay on Xs)
    __syncthreads();
#pragma unroll
    for (int r = 0; r < 8; r++)
#pragma unroll
        for (int j = 0; j < 4; j++)
            Rs[r * 1024 + warp * 128 + b0 + j] = acc[j][r];
    __syncthreads();

    // epilogue: thread = (b, hl)
    {
        const int b  = tid & 127;
        const int hl = tid >> 7;
        const int h  = h0 + hl;
        float gate[4];
#pragma unroll
        for (int g = 0; g < 4; g++) {
            float s = b_ih[g * H_ + h] + b_hh[g * H_ + h];
#pragma unroll
            for (int w = 0; w < 8; w++)
                s += Rs[(hl * 4 + g) * 1024 + w * 128 + b];
            gate[g] = s;
        }
        float gi = sigmoidf_(gate[0]);
        float gf = sigmoidf_(gate[1]);
        float gg = tanhf(gate[2]);
        float go = sigmoidf_(gate[3]);
        float cn = fmaf(gf, c_prev[b * H_ + h], gi * gg);
        float hn = go * tanhf(cn);
        c_out[b * H_ + h] = cn;
        h_out[b * H_ + h] = hn;
        if (LAYER == 1) g_X2T[(H_ + h) * B_ + b] = hn;
        if (h_dup)      h_dup[b * H_ + h] = hn;
    }
}

// ---------------- launch -----------------------------------------------------

extern "C" void kernel_launch(void* const* d_in, const int* in_sizes, int n_in,
                              void* d_out, int out_size)
{
    const float* embed   = (const float*)d_in[0];
    const float* enc     = (const float*)d_in[1];
    const float* hidden1 = (const float*)d_in[2];
    const float* cell1   = (const float*)d_in[3];
    const float* hidden2 = (const float*)d_in[4];
    const float* cell2   = (const float*)d_in[5];
    const float* w_ih1   = (const float*)d_in[6];
    const float* w_hh1   = (const float*)d_in[7];
    const float* b_ih1   = (const float*)d_in[8];
    const float* b_hh1   = (const float*)d_in[9];
    const float* w_ih2   = (const float*)d_in[10];
    const float* w_hh2   = (const float*)d_in[11];
    const float* b_ih2   = (const float*)d_in[12];
    const float* b_hh2   = (const float*)d_in[13];
    float* out = (float*)d_out;

    float* o_outputs = out;
    float* o_h1 = out + 32768;
    float* o_c1 = out + 65536;
    float* o_h2 = out + 98304;
    float* o_c2 = out + 131072;

    const int smem1 = (8 * 512 + 2 * 64 * 128) * 4;   // 81920
    const int smem2 = (8 * 768 + 2 * 64 * 128) * 4;   // 90112
    static bool attr_set = false;
    if (!attr_set) {
        cudaFuncSetAttribute(lstm_kernel<1>,
            cudaFuncAttributeMaxDynamicSharedMemorySize, smem1);
        cudaFuncSetAttribute(lstm_kernel<2>,
            cudaFuncAttributeMaxDynamicSharedMemorySize, smem2);
        attr_set = true;
    }

    attn_kernel<<<B_ * NSPLIT, 256>>>(enc, hidden1);
    combine_kernel<<<B_, 256>>>(hidden1, embed, hidden2);
    lstm_kernel<1><<<128, 256, smem1>>>(w_ih1, w_hh1, b_ih1, b_hh1, cell1,
                                        o_h1, o_c1, nullptr);
    lstm_kernel<2><<<128, 256, smem2>>>(w_ih2, w_hh2, b_ih2, b_hh2, cell2,
                                        o_h2, o_c2, o_outputs);
}